// round 4
// baseline (speedup 1.0000x reference)
#include <cuda_runtime.h>
#include <math_constants.h>

// Problem constants
#define NN    8192
#define CI    128      // IN_DIM == HID
#define HID   128
#define HEADS 4
#define HD    32
#define OUTD  40
#define RSQRT_HD 0.17677669529663687f  // 1/sqrt(32)

// ---------------- scratch (device globals; no allocation allowed) -------------
__device__ float g_h  [NN * HID];       // h = x@W_in^T + b_in
__device__ float g_qkv[NN * 3 * HID];   // qkv
__device__ float g_ao [NN * HID];       // attention output (N, HEADS*HD)
__device__ float g_h2 [NN * HID];       // h + relu(out_proj)

// ---------------- generic GEMM: C[M,CO] = A[M,128] @ W[CO,128]^T + b ----------
// optional epilogue: C = R + relu(C)   (residual add, R stride == CO)
// Tile: 64 rows x 64 cols per CTA, 256 threads, 4x4 microtile.
// A and W staged through smem and transposed for conflict-free vector reads.

#define GEMM_SMEM_FLOATS (2*128*64 + 64*132)   // At + Wt + staging
#define GEMM_SMEM_BYTES  (GEMM_SMEM_FLOATS * 4)

__global__ __launch_bounds__(256, 2)
void gemm_k(const float* __restrict__ A, const float* __restrict__ W,
            const float* __restrict__ bias, const float* __restrict__ R,
            float* __restrict__ C, int M, int CO, int relu_res)
{
    extern __shared__ float sm[];
    float* At  = sm;                 // [128][64] transposed A tile
    float* Wt  = sm + 128*64;        // [128][64] transposed W tile
    float* Stg = sm + 2*128*64;      // [64][132] staging

    const int r0  = blockIdx.x * 64;
    const int c0  = blockIdx.y * 64;
    const int tid = threadIdx.x;

    // ---- stage A (coalesced) ----
    {
        const float4* Af4 = (const float4*)(A + (size_t)r0 * CI);
        float4* Sf4 = (float4*)Stg;
        #pragma unroll
        for (int i = 0; i < 8; i++) {
            int idx = tid + 256*i;          // 2048 float4s
            int r = idx >> 5, d4 = idx & 31;
            Sf4[r*33 + d4] = Af4[r*32 + d4];
        }
    }
    __syncthreads();
    // ---- transpose A -> At[d][r] ----
    {
        #pragma unroll
        for (int i = 0; i < 8; i++) {
            int idx = tid + 256*i;
            int r = idx & 63, d4 = idx >> 6;
            float4 v = *(const float4*)&Stg[r*132 + d4*4];
            At[(4*d4+0)*64 + r] = v.x;
            At[(4*d4+1)*64 + r] = v.y;
            At[(4*d4+2)*64 + r] = v.z;
            At[(4*d4+3)*64 + r] = v.w;
        }
    }
    __syncthreads();
    // ---- stage W (bounds-guarded, zero fill) ----
    {
        const float4* Wf4 = (const float4*)W;
        float4* Sf4 = (float4*)Stg;
        #pragma unroll
        for (int i = 0; i < 8; i++) {
            int idx = tid + 256*i;
            int c = idx >> 5, d4 = idx & 31;
            float4 v = make_float4(0.f, 0.f, 0.f, 0.f);
            if (c0 + c < CO) v = Wf4[(size_t)(c0 + c)*32 + d4];
            Sf4[c*33 + d4] = v;
        }
    }
    __syncthreads();
    // ---- transpose W -> Wt[d][c] ----
    {
        #pragma unroll
        for (int i = 0; i < 8; i++) {
            int idx = tid + 256*i;
            int c = idx & 63, d4 = idx >> 6;
            float4 v = *(const float4*)&Stg[c*132 + d4*4];
            Wt[(4*d4+0)*64 + c] = v.x;
            Wt[(4*d4+1)*64 + c] = v.y;
            Wt[(4*d4+2)*64 + c] = v.z;
            Wt[(4*d4+3)*64 + c] = v.w;
        }
    }
    __syncthreads();

    // ---- compute 4x4 microtile ----
    const int tr = tid >> 4;   // 0..15  -> rows tr*4..tr*4+3
    const int tc = tid & 15;   // 0..15  -> cols tc*4..tc*4+3
    float acc[4][4];
    #pragma unroll
    for (int i = 0; i < 4; i++)
        #pragma unroll
        for (int j = 0; j < 4; j++) acc[i][j] = 0.f;

    #pragma unroll 8
    for (int d = 0; d < 128; d++) {
        float4 a = *(const float4*)&At[d*64 + tr*4];
        float4 w = *(const float4*)&Wt[d*64 + tc*4];
        float av[4] = {a.x, a.y, a.z, a.w};
        float wv[4] = {w.x, w.y, w.z, w.w};
        #pragma unroll
        for (int i = 0; i < 4; i++)
            #pragma unroll
            for (int j = 0; j < 4; j++)
                acc[i][j] = fmaf(av[i], wv[j], acc[i][j]);
    }

    // ---- epilogue ----
    #pragma unroll
    for (int i = 0; i < 4; i++) {
        int r = r0 + tr*4 + i;
        #pragma unroll
        for (int j = 0; j < 4; j++) {
            int c = c0 + tc*4 + j;
            if (c < CO) {
                float v = acc[i][j] + bias[c];
                if (relu_res) v = R[(size_t)r*CO + c] + fmaxf(v, 0.f);
                C[(size_t)r*CO + c] = v;
            }
        }
    }
}

// ---------------- fused flash attention (fp32, online softmax) ----------------
// grid = N/64 CTAs, 256 threads. Thread t: head = t>>6, query-in-block = t&63.
// All 4 heads handled in one CTA so the sp/bias tile is read ONCE from HBM.
// Smem: K tile [4][64][8]f4 (32KB), V tile same (32KB), bias [64k][67] (17KB).

#define BM 64
#define BN 64
#define ATTN_SMEM_BYTES (2*2048*16 + 64*67*4)

__device__ __forceinline__ float bias_of(float s, float scale)
{
    if (isnan(s) || isinf(s)) s = -1.0f;       // nan_to_num(sp, -1)
    float t = 1.0f / s;                         // 1/0 -> inf
    if (isnan(t) || isinf(t)) t = 0.0f;         // nan_to_num(1/sp, 0)
    return scale * t;
}

__global__ __launch_bounds__(256, 1)
void attn_k(const float* __restrict__ qkv, const float* __restrict__ sp,
            const float* __restrict__ scale_ptr, float* __restrict__ out)
{
    extern __shared__ float sm[];
    float4* Ksh = (float4*)sm;           // [head][j][u]  head*512 + j*8 + u
    float4* Vsh = Ksh + 2048;
    float*  Bsh = (float*)(Vsh + 2048);  // [j][qi], stride 67

    const int tid  = threadIdx.x;
    const int head = tid >> 6;
    const int qi   = tid & 63;
    const int q0   = blockIdx.x * BM;
    const float scale = scale_ptr[0];

    const float4* qkvf4 = (const float4*)qkv;   // row stride 96 f4
    const float4* spf4  = (const float4*)sp;    // row stride 2048 f4

    // load this thread's query row (HD=32 floats) into registers
    float4 q[8];
    #pragma unroll
    for (int u = 0; u < 8; u++)
        q[u] = qkvf4[(size_t)(q0 + qi)*96 + head*8 + u];

    float4 o[8];
    #pragma unroll
    for (int u = 0; u < 8; u++) o[u] = make_float4(0.f, 0.f, 0.f, 0.f);
    float m = -CUDART_INF_F, l = 0.f;

    for (int kb = 0; kb < NN / BN; kb++) {
        const int k0 = kb * BN;
        // ---- load K/V tiles (all heads), coalesced ----
        #pragma unroll
        for (int i = 0; i < 8; i++) {
            int idx = tid + 256*i;          // 2048 f4 per tile
            int j = idx >> 5, c = idx & 31;
            int dst = (c >> 3)*512 + j*8 + (c & 7);
            Ksh[dst] = qkvf4[(size_t)(k0 + j)*96 + 32 + c];
            Vsh[dst] = qkvf4[(size_t)(k0 + j)*96 + 64 + c];
        }
        // ---- load + transform bias tile, store transposed [key][query] ----
        #pragma unroll
        for (int i = 0; i < 4; i++) {
            int idx = tid + 256*i;          // 1024 f4
            int qq = idx >> 4, c4 = idx & 15;
            float4 s4 = spf4[(size_t)(q0 + qq)*2048 + kb*16 + c4];
            Bsh[(4*c4+0)*67 + qq] = bias_of(s4.x, scale);
            Bsh[(4*c4+1)*67 + qq] = bias_of(s4.y, scale);
            Bsh[(4*c4+2)*67 + qq] = bias_of(s4.z, scale);
            Bsh[(4*c4+3)*67 + qq] = bias_of(s4.w, scale);
        }
        __syncthreads();

        const float4* Kh = Ksh + head*512;
        const float4* Vh = Vsh + head*512;

        #pragma unroll
        for (int jc = 0; jc < 4; jc++) {      // 4 chunks of 16 keys
            float sv[16];
            float cm = -CUDART_INF_F;
            #pragma unroll
            for (int jj = 0; jj < 16; jj++) {
                int j = jc*16 + jj;
                const float4* kp = Kh + j*8;
                float acc = 0.f;
                #pragma unroll
                for (int u = 0; u < 8; u++) {
                    float4 k4 = kp[u];
                    acc = fmaf(q[u].x, k4.x, acc);
                    acc = fmaf(q[u].y, k4.y, acc);
                    acc = fmaf(q[u].z, k4.z, acc);
                    acc = fmaf(q[u].w, k4.w, acc);
                }
                float s = fmaf(acc, RSQRT_HD, Bsh[j*67 + qi]);
                sv[jj] = s;
                cm = fmaxf(cm, s);
            }
            if (cm > m) {
                float corr = __expf(m - cm);   // first block: exp(-inf)=0
                l *= corr;
                #pragma unroll
                for (int u = 0; u < 8; u++) {
                    o[u].x *= corr; o[u].y *= corr; o[u].z *= corr; o[u].w *= corr;
                }
                m = cm;
            }
            #pragma unroll
            for (int jj = 0; jj < 16; jj++) {
                float p = __expf(sv[jj] - m);
                l += p;
                const float4* vp = Vh + (jc*16 + jj)*8;
                #pragma unroll
                for (int u = 0; u < 8; u++) {
                    float4 v4 = vp[u];
                    o[u].x = fmaf(p, v4.x, o[u].x);
                    o[u].y = fmaf(p, v4.y, o[u].y);
                    o[u].z = fmaf(p, v4.z, o[u].z);
                    o[u].w = fmaf(p, v4.w, o[u].w);
                }
            }
        }
        __syncthreads();
    }

    const float inv = 1.0f / l;
    float4* of4 = (float4*)out;                 // row stride 32 f4
    #pragma unroll
    for (int u = 0; u < 8; u++) {
        float4 t;
        t.x = o[u].x * inv; t.y = o[u].y * inv;
        t.z = o[u].z * inv; t.w = o[u].w * inv;
        of4[(size_t)(q0 + qi)*32 + head*8 + u] = t;
    }
}

// ---------------- log_softmax over last dim (40), in-place ----------------
__global__ __launch_bounds__(256)
void logsoftmax_k(float* __restrict__ io)
{
    int row  = blockIdx.x * 8 + (threadIdx.x >> 5);
    int lane = threadIdx.x & 31;
    float* p = io + (size_t)row * OUTD;

    float a = p[lane];
    float b = (lane < 8) ? p[lane + 32] : -CUDART_INF_F;

    float mx = fmaxf(a, b);
    #pragma unroll
    for (int off = 16; off; off >>= 1)
        mx = fmaxf(mx, __shfl_xor_sync(0xffffffffu, mx, off));

    float e = __expf(a - mx) + ((lane < 8) ? __expf(b - mx) : 0.f);
    #pragma unroll
    for (int off = 16; off; off >>= 1)
        e += __shfl_xor_sync(0xffffffffu, e, off);

    float lse = mx + logf(e);
    p[lane] = a - lse;
    if (lane < 8) p[lane + 32] = b - lse;
}

// ---------------- launch ----------------
extern "C" void kernel_launch(void* const* d_in, const int* in_sizes, int n_in,
                              void* d_out, int out_size)
{
    (void)in_sizes; (void)n_in; (void)out_size;
    const float* x     = (const float*)d_in[0];
    // d_in[1] = pos_enc, unused in forward (faithful to reference)
    const float* sp    = (const float*)d_in[2];
    const float* W_in  = (const float*)d_in[3];
    const float* b_in  = (const float*)d_in[4];
    const float* ipw   = (const float*)d_in[5];
    const float* ipb   = (const float*)d_in[6];
    const float* opw   = (const float*)d_in[7];
    const float* opb   = (const float*)d_in[8];
    const float* Wout  = (const float*)d_in[9];
    const float* bout  = (const float*)d_in[10];
    const float* scale = (const float*)d_in[11];
    float* out = (float*)d_out;

    float *gh, *gqkv, *gao, *gh2;
    cudaGetSymbolAddress((void**)&gh,   g_h);
    cudaGetSymbolAddress((void**)&gqkv, g_qkv);
    cudaGetSymbolAddress((void**)&gao,  g_ao);
    cudaGetSymbolAddress((void**)&gh2,  g_h2);

    cudaFuncSetAttribute(gemm_k, cudaFuncAttributeMaxDynamicSharedMemorySize, GEMM_SMEM_BYTES);
    cudaFuncSetAttribute(attn_k, cudaFuncAttributeMaxDynamicSharedMemorySize, ATTN_SMEM_BYTES);

    // h = x @ W_in^T + b_in
    gemm_k<<<dim3(NN/64, 2), 256, GEMM_SMEM_BYTES>>>(x, W_in, b_in, nullptr, gh, NN, HID, 0);
    // qkv = h @ in_proj_w^T + in_proj_b
    gemm_k<<<dim3(NN/64, 6), 256, GEMM_SMEM_BYTES>>>(gh, ipw, ipb, nullptr, gqkv, NN, 3*HID, 0);
    // attention (bias computed inline from sp)
    attn_k<<<NN/BM, 256, ATTN_SMEM_BYTES>>>(gqkv, sp, scale, gao);
    // h2 = h + relu(ao @ out_proj^T + out_proj_b)
    gemm_k<<<dim3(NN/64, 2), 256, GEMM_SMEM_BYTES>>>(gao, opw, opb, gh, gh2, NN, HID, 1);
    // logits = h2 @ W_out^T + b_out  (written straight to d_out)
    gemm_k<<<dim3(NN/64, 1), 256, GEMM_SMEM_BYTES>>>(gh2, Wout, bout, nullptr, out, NN, OUTD, 0);
    // log_softmax in-place
    logsoftmax_k<<<NN/8, 256>>>(out);
}